// round 13
// baseline (speedup 1.0000x reference)
#include <cuda_runtime.h>
#include <cstdint>

// EMA scan: sta_t = 0.4*sta_{t-1} + 0.6*x_t  (a = 0.4, a^16 ~ 4.3e-7 -> 16-step warm-up)
// Half-row chunks: S_CHUNK=3000, 250 segments of 12 steps, 1 batch row per block.
// Prefix amplification = 16/3000 (chunk 1 only); chunk 0 starts from the true zero state.

#define T_LEN   6000
#define CH      3
#define ROW_F   (T_LEN * CH)            // 18000 floats per batch row
#define WARM    16                      // warm-up steps (a^16 ~ 4.3e-7)
#define SEG     12                      // per-thread segment (36-float stride: conflict-free fl4 banks)
#define SEGS    250                     // segments per chunk
#define S_CHUNK (SEG * SEGS)            // 3000 timesteps per chunk
#define THREADS 256
#define TILE_T  (WARM + S_CHUNK)        // 3016
#define TILE_F  (TILE_T * CH)           // 9048 floats = 36192 B
#define TILE_Q  (TILE_F / 4)            // 2262 quads
#define OUT_Q   (S_CHUNK * CH / 4)      // 2250 quads
#define W_A     0.4f
#define W_W     0.6f

// one EMA step over 3 channels
#define STEP(X0, X1, X2)                         \
    c0 = fmaf(W_A, c0, W_W * (X0));              \
    c1 = fmaf(W_A, c1, W_W * (X1));              \
    c2 = fmaf(W_A, c2, W_W * (X2));

__global__ __launch_bounds__(THREADS)
void ema_scan_kernel(const float* __restrict__ in, float* __restrict__ out) {
    __shared__ float4 tile4[TILE_Q];               // 36192 B
    float* tile = reinterpret_cast<float*>(tile4);

    const int tid   = threadIdx.x;
    const int chunk = blockIdx.x & 1;              // 0: t[0,3000), 1: t[3000,6000)
    const int row   = blockIdx.x >> 1;
    const int cs    = chunk * S_CHUNK;
    const int gbase = cs * CH - WARM * CH;         // -48 (chunk 0) or 8952 (chunk 1)

    const float* rowin = in + (size_t)row * ROW_F;

    // ---- stage GMEM -> SMEM via cp.async ----
    {
        const uint32_t sbase = (uint32_t)__cvta_generic_to_shared(tile);
        if (chunk == 0) {
            // first 12 quads (48 floats = 16 warm steps) zero-filled: true zero init state
            #pragma unroll
            for (int it = 0; it < 9; it++) {
                int q = tid + it * THREADS;
                if (q < TILE_Q) {
                    int g   = gbase + q * 4;
                    int gc  = g >= 0 ? g : 0;
                    int sz  = g >= 0 ? 16 : 0;     // 0 => full zero-fill
                    asm volatile("cp.async.cg.shared.global [%0], [%1], 16, %2;\n"
                                 :: "r"(sbase + (uint32_t)q * 16), "l"(rowin + gc), "r"(sz));
                }
            }
        } else {
            // fully in-range: [8952, 18000) exactly
            #pragma unroll
            for (int it = 0; it < 9; it++) {
                int q = tid + it * THREADS;
                if (q < TILE_Q) {
                    asm volatile("cp.async.cg.shared.global [%0], [%1], 16;\n"
                                 :: "r"(sbase + (uint32_t)q * 16), "l"(rowin + gbase + q * 4));
                }
            }
        }
        asm volatile("cp.async.commit_group;\n");
        asm volatile("cp.async.wait_group 0;\n");
    }
    __syncthreads();

    float c0 = 0.f, c1 = 0.f, c2 = 0.f;

    // ---- phase 1: per-segment warm-up carry (16 steps = 12 quads, reads only) ----
    if (tid < SEGS) {
        const float4* wp = reinterpret_cast<const float4*>(tile + tid * (SEG * CH));
        #pragma unroll
        for (int g3 = 0; g3 < WARM / 4; g3++) {    // 4 groups of 3 quads = 4 steps each
            float4 q0 = wp[3 * g3 + 0];
            float4 q1 = wp[3 * g3 + 1];
            float4 q2 = wp[3 * g3 + 2];
            STEP(q0.x, q0.y, q0.z)
            STEP(q0.w, q1.x, q1.y)
            STEP(q1.z, q1.w, q2.x)
            STEP(q2.y, q2.z, q2.w)
        }
    }
    __syncthreads();   // all warm-up reads complete before in-place overwrite

    // ---- phase 2: in-place segment scan (12 steps = 9 quads) ----
    if (tid < SEGS) {
        float4* sp = reinterpret_cast<float4*>(tile + WARM * CH + tid * (SEG * CH));
        #pragma unroll
        for (int g3 = 0; g3 < SEG / 4; g3++) {
            float4 q0 = sp[3 * g3 + 0];
            float4 q1 = sp[3 * g3 + 1];
            float4 q2 = sp[3 * g3 + 2];
            STEP(q0.x, q0.y, q0.z)  q0.x = c0; q0.y = c1; q0.z = c2;
            STEP(q0.w, q1.x, q1.y)  q0.w = c0; q1.x = c1; q1.y = c2;
            STEP(q1.z, q1.w, q2.x)  q1.z = c0; q1.w = c1; q2.x = c2;
            STEP(q2.y, q2.z, q2.w)  q2.y = c0; q2.z = c1; q2.w = c2;
            sp[3 * g3 + 0] = q0;
            sp[3 * g3 + 1] = q1;
            sp[3 * g3 + 2] = q2;
        }
    }
    __syncthreads();

    // ---- coalesced float4 streaming store: SMEM chunk region -> GMEM ----
    {
        float4* rowout = reinterpret_cast<float4*>(out + (size_t)row * ROW_F + cs * CH);
        const float4* src = reinterpret_cast<const float4*>(tile + WARM * CH);
        #pragma unroll
        for (int it = 0; it < 9; it++) {
            int q = tid + it * THREADS;
            if (q < OUT_Q)
                __stcs(rowout + q, src[q]);
        }
    }
}

extern "C" void kernel_launch(void* const* d_in, const int* in_sizes, int n_in,
                              void* d_out, int out_size) {
    const float* wave = (const float*)d_in[0];
    float* out = (float*)d_out;
    const int B = in_sizes[0] / ROW_F;             // 4096
    const int blocks = B * 2;                      // 8192 (2 half-row chunks per row)
    ema_scan_kernel<<<blocks, THREADS>>>(wave, out);
}

// round 14
// speedup vs baseline: 1.2502x; 1.2502x over previous
#include <cuda_runtime.h>
#include <cstdint>

// EMA scan: sta_t = 0.4*sta_{t-1} + 0.6*x_t  (a = 0.4, a^16 ~ 4.3e-7 -> 16-step warm-up)
// R9 block granularity (128 thr, 16384 blocks) + reduced amplification (2.1%).

#define T_LEN   6000
#define CH      3
#define ROW_F   (T_LEN * CH)            // 18000 floats per batch row
#define WARM    16                      // warm-up steps (a^16 ~ 4.3e-7)
#define SEG     12                      // per-thread segment (36-float stride: conflict-free fl4 banks)
#define SEGS    64                      // segments per chunk
#define S_CHUNK (SEG * SEGS)            // 768 timesteps per chunk
#define NB      2                       // batch rows per block
#define THREADS (NB * SEGS)             // 128
#define TILE_T  (WARM + S_CHUNK)        // 784
#define TILE_F  (TILE_T * CH)           // 2352 floats per row
#define TILE_Q  (NB * TILE_F / 4)       // 1176 quads
#define OUT_F   (S_CHUNK * CH)          // 2304 floats per row
#define OUT_Q   (NB * OUT_F / 4)        // 1152 quads
#define N_CHUNKS 8                      // covers 6144; tail guarded
#define W_A     0.4f
#define W_W     0.6f

// one EMA step over 3 channels
#define STEP(X0, X1, X2)                         \
    c0 = fmaf(W_A, c0, W_W * (X0));              \
    c1 = fmaf(W_A, c1, W_W * (X1));              \
    c2 = fmaf(W_A, c2, W_W * (X2));

__global__ __launch_bounds__(THREADS)
void ema_scan_kernel(const float* __restrict__ in, float* __restrict__ out) {
    __shared__ float4 tile4[TILE_Q];               // 18816 B
    float* tile = reinterpret_cast<float*>(tile4);

    const int tid   = threadIdx.x;
    const int chunk = blockIdx.x & (N_CHUNKS - 1);
    const int row0  = (blockIdx.x >> 3) * NB;
    const int cs    = chunk * S_CHUNK;             // chunk start timestep
    const int gbase = cs * CH - WARM * CH;         // float offset of tile start (mult of 4)

    // ---- stage GMEM -> SMEM via cp.async (zero-fill for OOB quads) ----
    // OOB-low -> zeros == true zero init state; OOB-high only in tail chunk (unused).
    {
        const uint32_t sbase = (uint32_t)__cvta_generic_to_shared(tile);
        #pragma unroll
        for (int it = 0; it < 10; it++) {
            int q = tid + it * THREADS;
            if (q < TILE_Q) {
                int f  = q * 4;
                int r  = f / TILE_F;
                int fr = f - r * TILE_F;
                int g  = gbase + fr;
                int gc = g < 0 ? 0 : (g > ROW_F - 4 ? ROW_F - 4 : g);
                int sz = (g >= 0 && g <= ROW_F - 4) ? 16 : 0;       // 0 => full zero-fill
                const float* src = in + (size_t)(row0 + r) * ROW_F + gc;
                asm volatile("cp.async.cg.shared.global [%0], [%1], 16, %2;\n"
                             :: "r"(sbase + (uint32_t)q * 16), "l"(src), "r"(sz));
            }
        }
        asm volatile("cp.async.commit_group;\n");
        asm volatile("cp.async.wait_group 0;\n");
    }
    __syncthreads();

    const int s = tid & (SEGS - 1);      // segment within chunk
    const int r = tid >> 6;              // batch row within block
    float* rowp = tile + r * TILE_F;

    float c0 = 0.f, c1 = 0.f, c2 = 0.f;

    // ---- phase 1: warm-up carry, float4 reads (16 steps = 12 quads, reads only) ----
    {
        const float4* wp = reinterpret_cast<const float4*>(rowp + s * (SEG * CH)); // 36-float stride
        #pragma unroll
        for (int g3 = 0; g3 < WARM / 4; g3++) {    // 4 groups of 3 quads = 4 steps each
            float4 q0 = wp[3 * g3 + 0];
            float4 q1 = wp[3 * g3 + 1];
            float4 q2 = wp[3 * g3 + 2];
            STEP(q0.x, q0.y, q0.z)
            STEP(q0.w, q1.x, q1.y)
            STEP(q1.z, q1.w, q2.x)
            STEP(q2.y, q2.z, q2.w)
        }
    }
    __syncthreads();   // all warm-up reads complete before in-place overwrite

    // ---- phase 2: in-place segment scan, float4 (12 steps = 9 quads) ----
    {
        float4* sp = reinterpret_cast<float4*>(rowp + WARM * CH + s * (SEG * CH));
        #pragma unroll
        for (int g3 = 0; g3 < SEG / 4; g3++) {
            float4 q0 = sp[3 * g3 + 0];
            float4 q1 = sp[3 * g3 + 1];
            float4 q2 = sp[3 * g3 + 2];
            STEP(q0.x, q0.y, q0.z)  q0.x = c0; q0.y = c1; q0.z = c2;
            STEP(q0.w, q1.x, q1.y)  q0.w = c0; q1.x = c1; q1.y = c2;
            STEP(q1.z, q1.w, q2.x)  q1.z = c0; q1.w = c1; q2.x = c2;
            STEP(q2.y, q2.z, q2.w)  q2.y = c0; q2.z = c1; q2.w = c2;
            sp[3 * g3 + 0] = q0;
            sp[3 * g3 + 1] = q1;
            sp[3 * g3 + 2] = q2;
        }
    }
    __syncthreads();

    // ---- coalesced float4 store: SMEM chunk region -> GMEM ----
    {
        const int obase = cs * CH;
        #pragma unroll
        for (int it = 0; it < 9; it++) {
            int q = tid + it * THREADS;
            if (q < OUT_Q) {
                int f  = q * 4;
                int r2 = f / OUT_F;
                int fr = f - r2 * OUT_F;
                int g  = obase + fr;
                if (g < ROW_F)
                    *reinterpret_cast<float4*>(out + (size_t)(row0 + r2) * ROW_F + g) =
                        *reinterpret_cast<const float4*>(&tile[r2 * TILE_F + WARM * CH + fr]);
            }
        }
    }
}

extern "C" void kernel_launch(void* const* d_in, const int* in_sizes, int n_in,
                              void* d_out, int out_size) {
    const float* wave = (const float*)d_in[0];
    float* out = (float*)d_out;
    const int B = in_sizes[0] / ROW_F;             // 4096
    const int blocks = (B / NB) * N_CHUNKS;        // 16384
    ema_scan_kernel<<<blocks, THREADS>>>(wave, out);
}